// round 1
// baseline (speedup 1.0000x reference)
#include <cuda_runtime.h>
#include <cuda_bf16.h>
#include <math.h>

#define NN 100000
#define EE 3200000

// ---------------- scratch (__device__ globals; no allocs allowed) ----------------
__device__ float g_h1[(size_t)NN * 64];   // 25.6 MB
__device__ float g_h2[(size_t)NN * 64];   // 25.6 MB
__device__ int   g_counts[NN];
__device__ int   g_offsets[NN + 1];
__device__ int   g_cursor[NN];
__device__ int   g_csr[EE];               // 12.8 MB (src sorted by dst)
__device__ float g_dinv[NN];
__device__ int   g_is64;

// ---------------- dtype detection: int64 vs int32 edge_index ----------------
__global__ void k_detect(const void* edges) {
    if (blockIdx.x == 0 && threadIdx.x == 0) {
        const unsigned* w = (const unsigned*)edges;
        int is64 = 1;
        #pragma unroll
        for (int i = 1; i < 64; i += 2) {
            if (w[i] != 0u) { is64 = 0; break; }
        }
        g_is64 = is64;
    }
}

__device__ __forceinline__ int edge_val(const void* p, long long i, int is64) {
    if (is64) return (int)((const long long*)p)[i];
    return ((const int*)p)[i];
}

// ---------------- zero counts ----------------
__global__ void k_zero() {
    int i = blockIdx.x * blockDim.x + threadIdx.x;
    if (i < NN) g_counts[i] = 0;
}

// ---------------- in-degree histogram over dst ----------------
__global__ void k_hist(const void* edges) {
    int e = blockIdx.x * blockDim.x + threadIdx.x;
    if (e >= EE) return;
    int is64 = g_is64;
    int d = edge_val(edges, (long long)EE + e, is64);
    atomicAdd(&g_counts[d], 1);
}

// ---------------- single-block chunked exclusive scan + dinv ----------------
__global__ void k_scan() {
    __shared__ int wsum[32];
    __shared__ int carry_s;
    int t = threadIdx.x, lane = t & 31, wid = t >> 5;
    if (t == 0) carry_s = 0;
    __syncthreads();
    for (int base = 0; base < NN; base += 1024) {
        int idx = base + t;
        int v = (idx < NN) ? g_counts[idx] : 0;
        int x = v;
        #pragma unroll
        for (int off = 1; off < 32; off <<= 1) {
            int y = __shfl_up_sync(0xffffffffu, x, off);
            if (lane >= off) x += y;
        }
        if (lane == 31) wsum[wid] = x;
        __syncthreads();
        if (wid == 0) {
            int s = wsum[lane];
            #pragma unroll
            for (int off = 1; off < 32; off <<= 1) {
                int y = __shfl_up_sync(0xffffffffu, s, off);
                if (lane >= off) s += y;
            }
            wsum[lane] = s;
        }
        __syncthreads();
        int incl = x + (wid > 0 ? wsum[wid - 1] : 0);
        int carry = carry_s;
        __syncthreads();
        if (idx < NN) {
            int excl = carry + incl - v;
            g_offsets[idx] = excl;
            g_cursor[idx]  = excl;
            g_dinv[idx]    = rsqrtf((float)(v + 1));
        }
        if (t == 1023) carry_s = carry + incl;
        __syncthreads();
    }
    if (t == 0) g_offsets[NN] = carry_s;
}

// ---------------- CSR fill ----------------
__global__ void k_fill(const void* edges) {
    int e = blockIdx.x * blockDim.x + threadIdx.x;
    if (e >= EE) return;
    int is64 = g_is64;
    int s = edge_val(edges, e, is64);
    int d = edge_val(edges, (long long)EE + e, is64);
    int pos = atomicAdd(&g_cursor[d], 1);
    g_csr[pos] = s;
}

// ---------------- dense GEMM: C[N,64] = X[N,K] @ W[K,64] (no bias) ----------------
template <int K>
__global__ __launch_bounds__(256)
void k_gemm(const float* __restrict__ X, const float* __restrict__ W,
            float* __restrict__ C) {
    __shared__ float Ws[K * 64];
    for (int i = threadIdx.x; i < K * 16; i += 256) {
        ((float4*)Ws)[i] = ((const float4*)W)[i];
    }
    __syncthreads();
    int r = blockIdx.x * 256 + threadIdx.x;
    if (r >= NN) return;

    float acc[64];
    #pragma unroll
    for (int j = 0; j < 64; j++) acc[j] = 0.f;

    const float4* xr = (const float4*)(X + (size_t)r * K);
    #pragma unroll 2
    for (int k4 = 0; k4 < K / 4; k4++) {
        float4 xv = xr[k4];
        float xk[4] = {xv.x, xv.y, xv.z, xv.w};
        #pragma unroll
        for (int kk = 0; kk < 4; kk++) {
            const float4* wr = (const float4*)&Ws[(k4 * 4 + kk) * 64];
            float xs = xk[kk];
            #pragma unroll
            for (int j4 = 0; j4 < 16; j4++) {
                float4 w = wr[j4];
                acc[j4 * 4 + 0] += xs * w.x;
                acc[j4 * 4 + 1] += xs * w.y;
                acc[j4 * 4 + 2] += xs * w.z;
                acc[j4 * 4 + 3] += xs * w.w;
            }
        }
    }
    float4* cr = (float4*)(C + (size_t)r * 64);
    #pragma unroll
    for (int j4 = 0; j4 < 16; j4++) {
        float4 o;
        o.x = acc[j4 * 4 + 0]; o.y = acc[j4 * 4 + 1];
        o.z = acc[j4 * 4 + 2]; o.w = acc[j4 * 4 + 3];
        cr[j4] = o;
    }
}

// ---------------- aggregation: out[v] = dinv[v]*(sum_e h[src]*dinv[src] + h[v]*dinv[v]) + b
// warp per node; lanes cover 64 channels (2 each); CSR gather, register accumulate.
__global__ __launch_bounds__(256)
void k_agg(const float* __restrict__ h, const float* __restrict__ b,
           float* __restrict__ out) {
    int v = blockIdx.x * 8 + (threadIdx.x >> 5);
    int lane = threadIdx.x & 31;
    if (v >= NN) return;
    int beg = g_offsets[v];
    int end = g_offsets[v + 1];
    float dv = g_dinv[v];

    float acc0 = 0.f, acc1 = 0.f;
    for (int e = beg; e < end; e += 32) {
        int cnt = min(32, end - e);
        int s = 0; float w = 0.f;
        if (lane < cnt) {
            s = g_csr[e + lane];
            w = g_dinv[s];
        }
        for (int i = 0; i < cnt; i++) {
            int   si = __shfl_sync(0xffffffffu, s, i);
            float wi = __shfl_sync(0xffffffffu, w, i);
            const float* hr = h + (size_t)si * 64;
            acc0 += hr[lane]      * wi;
            acc1 += hr[lane + 32] * wi;
        }
    }
    const float* hv = h + (size_t)v * 64;
    acc0 += hv[lane]      * dv;
    acc1 += hv[lane + 32] * dv;
    out[(size_t)v * 64 + lane]      = acc0 * dv + b[lane];
    out[(size_t)v * 64 + lane + 32] = acc1 * dv + b[lane + 32];
}

// ---------------- fused MLP head: relu(h@lw1+lb1) -> relu(@lw2+lb2) -> @lw3+lb3 ----------------
__global__ __launch_bounds__(128)
void k_mlp(const float* __restrict__ h,
           const float* __restrict__ lw1, const float* __restrict__ lb1,
           const float* __restrict__ lw2, const float* __restrict__ lb2,
           const float* __restrict__ lw3, const float* __restrict__ lb3,
           float* __restrict__ out) {
    __shared__ float s_w1[64 * 64];
    __shared__ float s_w2[64 * 32];
    __shared__ float s_w3[32];
    __shared__ float s_b1[64];
    __shared__ float s_b2[32];
    __shared__ float s_b3;
    int t = threadIdx.x;
    for (int i = t; i < 64 * 16; i += 128) ((float4*)s_w1)[i] = ((const float4*)lw1)[i];
    for (int i = t; i < 64 * 8;  i += 128) ((float4*)s_w2)[i] = ((const float4*)lw2)[i];
    if (t < 32) s_w3[t] = lw3[t];
    if (t < 64) s_b1[t] = lb1[t];
    if (t < 32) s_b2[t] = lb2[t];
    if (t == 0) s_b3 = lb3[0];
    __syncthreads();

    int v = blockIdx.x * 128 + t;
    if (v >= NN) return;

    float in[64];
    const float4* hr = (const float4*)(h + (size_t)v * 64);
    #pragma unroll
    for (int i = 0; i < 16; i++) {
        float4 q = hr[i];
        in[4 * i + 0] = q.x; in[4 * i + 1] = q.y;
        in[4 * i + 2] = q.z; in[4 * i + 3] = q.w;
    }

    float t1[64];
    #pragma unroll
    for (int j = 0; j < 64; j += 4) {
        float a0 = s_b1[j], a1 = s_b1[j + 1], a2 = s_b1[j + 2], a3 = s_b1[j + 3];
        #pragma unroll
        for (int k = 0; k < 64; k++) {
            float4 w = *(const float4*)&s_w1[k * 64 + j];
            a0 += in[k] * w.x; a1 += in[k] * w.y;
            a2 += in[k] * w.z; a3 += in[k] * w.w;
        }
        t1[j]     = fmaxf(a0, 0.f);
        t1[j + 1] = fmaxf(a1, 0.f);
        t1[j + 2] = fmaxf(a2, 0.f);
        t1[j + 3] = fmaxf(a3, 0.f);
    }

    float t2[32];
    #pragma unroll
    for (int j = 0; j < 32; j += 4) {
        float a0 = s_b2[j], a1 = s_b2[j + 1], a2 = s_b2[j + 2], a3 = s_b2[j + 3];
        #pragma unroll
        for (int k = 0; k < 64; k++) {
            float4 w = *(const float4*)&s_w2[k * 32 + j];
            a0 += t1[k] * w.x; a1 += t1[k] * w.y;
            a2 += t1[k] * w.z; a3 += t1[k] * w.w;
        }
        t2[j]     = fmaxf(a0, 0.f);
        t2[j + 1] = fmaxf(a1, 0.f);
        t2[j + 2] = fmaxf(a2, 0.f);
        t2[j + 3] = fmaxf(a3, 0.f);
    }

    float o = s_b3;
    #pragma unroll
    for (int k = 0; k < 32; k++) o += t2[k] * s_w3[k];
    out[v] = o;
}

// ---------------- launcher ----------------
extern "C" void kernel_launch(void* const* d_in, const int* in_sizes, int n_in,
                              void* d_out, int out_size) {
    const float* x   = (const float*)d_in[0];
    const void*  edg = d_in[1];
    const float* W1  = (const float*)d_in[2];
    const float* b1  = (const float*)d_in[3];
    const float* W2  = (const float*)d_in[4];
    const float* b2  = (const float*)d_in[5];
    const float* lw1 = (const float*)d_in[6];
    const float* lb1 = (const float*)d_in[7];
    const float* lw2 = (const float*)d_in[8];
    const float* lb2 = (const float*)d_in[9];
    const float* lw3 = (const float*)d_in[10];
    const float* lb3 = (const float*)d_in[11];
    float* out = (float*)d_out;

    float* h1; cudaGetSymbolAddress((void**)&h1, g_h1);
    float* h2; cudaGetSymbolAddress((void**)&h2, g_h2);

    const int EB = (EE + 255) / 256;

    k_detect<<<1, 32>>>(edg);
    k_zero<<<(NN + 1023) / 1024, 1024>>>();
    k_hist<<<EB, 256>>>(edg);
    k_scan<<<1, 1024>>>();
    k_fill<<<EB, 256>>>(edg);

    // conv1: h1 = x @ W1 ; h2 = aggregate(h1) + b1
    k_gemm<128><<<(NN + 255) / 256, 256>>>(x, W1, h1);
    k_agg<<<(NN + 7) / 8, 256>>>(h1, b1, h2);

    // conv2: h1 = h2 @ W2 ; h2 = aggregate(h1) + b2
    k_gemm<64><<<(NN + 255) / 256, 256>>>(h2, W2, h1);
    k_agg<<<(NN + 7) / 8, 256>>>(h1, b2, h2);

    // MLP head
    k_mlp<<<(NN + 127) / 128, 128>>>(h2, lw1, lb1, lw2, lb2, lw3, lb3, out);
}

// round 2
// speedup vs baseline: 1.2422x; 1.2422x over previous
#include <cuda_runtime.h>
#include <cuda_bf16.h>
#include <math.h>

#define NN 100000
#define EE 3200000
#define NB 98   // (NN+1023)/1024 blocks for the scan

typedef unsigned long long ull;

// ---------------- scratch (__device__ globals; no allocs allowed) ----------------
__device__ float g_h1[(size_t)NN * 64];   // 25.6 MB
__device__ float g_h2[(size_t)NN * 64];   // 25.6 MB
__device__ int   g_counts[NN];
__device__ int   g_offsets[NN + 1];
__device__ int   g_cursor[NN];
__device__ int   g_csr[EE];               // 12.8 MB (src sorted by dst)
__device__ float g_dinv[NN];
__device__ int   g_bsums[NB];
__device__ int   g_is64;

// ---------------- packed f32x2 helpers ----------------
__device__ __forceinline__ void ffma2(ull& d, ull a, ull b) {
    asm("fma.rn.f32x2 %0, %1, %2, %0;" : "+l"(d) : "l"(a), "l"(b));
}
__device__ __forceinline__ ull bcast2(float x) {
    unsigned u = __float_as_uint(x);
    return ((ull)u << 32) | (ull)u;
}

// ---------------- dtype detection: int64 vs int32 edge_index ----------------
__global__ void k_detect(const void* edges) {
    if (blockIdx.x == 0 && threadIdx.x == 0) {
        const unsigned* w = (const unsigned*)edges;
        int is64 = 1;
        #pragma unroll
        for (int i = 1; i < 64; i += 2) {
            if (w[i] != 0u) { is64 = 0; break; }
        }
        g_is64 = is64;
    }
}

__device__ __forceinline__ int edge_val(const void* p, long long i, int is64) {
    if (is64) return (int)((const long long*)p)[i];
    return ((const int*)p)[i];
}

// ---------------- zero counts ----------------
__global__ void k_zero() {
    int i = blockIdx.x * blockDim.x + threadIdx.x;
    if (i < NN) g_counts[i] = 0;
}

// ---------------- in-degree histogram over dst ----------------
__global__ void k_hist(const void* edges) {
    int e = blockIdx.x * blockDim.x + threadIdx.x;
    if (e >= EE) return;
    int is64 = g_is64;
    int d = edge_val(edges, (long long)EE + e, is64);
    atomicAdd(&g_counts[d], 1);
}

// ---------------- parallel scan, phase 1: per-block sums ----------------
__global__ __launch_bounds__(1024)
void k_blocksum() {
    __shared__ int wsum[32];
    int t = threadIdx.x, lane = t & 31, wid = t >> 5;
    int idx = blockIdx.x * 1024 + t;
    int v = (idx < NN) ? g_counts[idx] : 0;
    #pragma unroll
    for (int off = 16; off > 0; off >>= 1)
        v += __shfl_down_sync(0xffffffffu, v, off);
    if (lane == 0) wsum[wid] = v;
    __syncthreads();
    if (wid == 0) {
        int s = wsum[lane];
        #pragma unroll
        for (int off = 16; off > 0; off >>= 1)
            s += __shfl_down_sync(0xffffffffu, s, off);
        if (lane == 0) g_bsums[blockIdx.x] = s;
    }
}

// ---------------- phase 2: 1-warp exclusive scan of block sums ----------------
__global__ void k_scansums() {
    int lane = threadIdx.x;
    int carry = 0;
    for (int base = 0; base < NB; base += 32) {
        int i = base + lane;
        int v = (i < NB) ? g_bsums[i] : 0;
        int x = v;
        #pragma unroll
        for (int off = 1; off < 32; off <<= 1) {
            int y = __shfl_up_sync(0xffffffffu, x, off);
            if (lane >= off) x += y;
        }
        if (i < NB) g_bsums[i] = carry + x - v;
        carry += __shfl_sync(0xffffffffu, x, 31);
    }
    if (lane == 0) g_offsets[NN] = carry;
}

// ---------------- phase 3: per-block scan + apply, write offsets/cursor/dinv ----------------
__global__ __launch_bounds__(1024)
void k_blockscan() {
    __shared__ int wsum[32];
    int t = threadIdx.x, lane = t & 31, wid = t >> 5;
    int idx = blockIdx.x * 1024 + t;
    int v = (idx < NN) ? g_counts[idx] : 0;
    int x = v;
    #pragma unroll
    for (int off = 1; off < 32; off <<= 1) {
        int y = __shfl_up_sync(0xffffffffu, x, off);
        if (lane >= off) x += y;
    }
    if (lane == 31) wsum[wid] = x;
    __syncthreads();
    if (wid == 0) {
        int s = wsum[lane];
        #pragma unroll
        for (int off = 1; off < 32; off <<= 1) {
            int y = __shfl_up_sync(0xffffffffu, s, off);
            if (lane >= off) s += y;
        }
        wsum[lane] = s;
    }
    __syncthreads();
    if (idx < NN) {
        int excl = g_bsums[blockIdx.x] + x - v + (wid > 0 ? wsum[wid - 1] : 0);
        g_offsets[idx] = excl;
        g_cursor[idx]  = excl;
        g_dinv[idx]    = rsqrtf((float)(v + 1));
    }
}

// ---------------- CSR fill ----------------
__global__ void k_fill(const void* edges) {
    int e = blockIdx.x * blockDim.x + threadIdx.x;
    if (e >= EE) return;
    int is64 = g_is64;
    int s = edge_val(edges, e, is64);
    int d = edge_val(edges, (long long)EE + e, is64);
    int pos = atomicAdd(&g_cursor[d], 1);
    g_csr[pos] = s;
}

// ---------------- dense GEMM: C[N,64] = X[N,K] @ W[K,64], packed f32x2 FMA ----------------
template <int K>
__global__ __launch_bounds__(256)
void k_gemm(const float* __restrict__ X, const float* __restrict__ W,
            float* __restrict__ C) {
    __shared__ float Ws[K * 64];
    for (int i = threadIdx.x; i < K * 16; i += 256) {
        ((float4*)Ws)[i] = ((const float4*)W)[i];
    }
    __syncthreads();
    int r = blockIdx.x * 256 + threadIdx.x;
    if (r >= NN) return;

    ull acc[32];
    #pragma unroll
    for (int j = 0; j < 32; j++) acc[j] = 0ull;

    const float4* xr = (const float4*)(X + (size_t)r * K);
    #pragma unroll 2
    for (int k4 = 0; k4 < K / 4; k4++) {
        float4 xv = xr[k4];
        float xk[4] = {xv.x, xv.y, xv.z, xv.w};
        #pragma unroll
        for (int kk = 0; kk < 4; kk++) {
            const ull* wr = (const ull*)&Ws[(k4 * 4 + kk) * 64];
            ull xs2 = bcast2(xk[kk]);
            #pragma unroll
            for (int j = 0; j < 32; j++) ffma2(acc[j], xs2, wr[j]);
        }
    }
    const float* af = (const float*)acc;
    float4* cr = (float4*)(C + (size_t)r * 64);
    #pragma unroll
    for (int j4 = 0; j4 < 16; j4++) {
        float4 o;
        o.x = af[4 * j4 + 0]; o.y = af[4 * j4 + 1];
        o.z = af[4 * j4 + 2]; o.w = af[4 * j4 + 3];
        cr[j4] = o;
    }
}

// ---------------- aggregation: out[v] = dinv[v]*(sum_e h[src]*dinv[src] + h[v]*dinv[v]) + b
// warp per node; lane covers channels {2l, 2l+1} via float2; 2-edge unroll for MLP.
__global__ __launch_bounds__(256)
void k_agg(const float* __restrict__ h, const float* __restrict__ b,
           float* __restrict__ out) {
    int v = blockIdx.x * 8 + (threadIdx.x >> 5);
    int lane = threadIdx.x & 31;
    if (v >= NN) return;
    int beg = g_offsets[v];
    int end = g_offsets[v + 1];
    float dv = g_dinv[v];

    const float2* H = (const float2*)h;
    float2 accA = make_float2(0.f, 0.f);
    float2 accB = make_float2(0.f, 0.f);

    for (int e = beg; e < end; e += 32) {
        int cnt = min(32, end - e);
        int s = 0; float w = 0.f;
        if (lane < cnt) {
            s = g_csr[e + lane];
            w = g_dinv[s];
        }
        int i = 0;
        for (; i + 1 < cnt; i += 2) {
            int   si0 = __shfl_sync(0xffffffffu, s, i);
            float wi0 = __shfl_sync(0xffffffffu, w, i);
            int   si1 = __shfl_sync(0xffffffffu, s, i + 1);
            float wi1 = __shfl_sync(0xffffffffu, w, i + 1);
            float2 a = H[(size_t)si0 * 32 + lane];
            float2 c = H[(size_t)si1 * 32 + lane];
            accA.x += a.x * wi0; accA.y += a.y * wi0;
            accB.x += c.x * wi1; accB.y += c.y * wi1;
        }
        if (i < cnt) {
            int   si = __shfl_sync(0xffffffffu, s, i);
            float wi = __shfl_sync(0xffffffffu, w, i);
            float2 a = H[(size_t)si * 32 + lane];
            accA.x += a.x * wi; accA.y += a.y * wi;
        }
    }
    float2 hv = H[(size_t)v * 32 + lane];
    float ax = accA.x + accB.x + hv.x * dv;
    float ay = accA.y + accB.y + hv.y * dv;
    float2 bb = ((const float2*)b)[lane];
    float2 o;
    o.x = ax * dv + bb.x;
    o.y = ay * dv + bb.y;
    ((float2*)out)[(size_t)v * 32 + lane] = o;
}

// ---------------- fused MLP head, packed f32x2 FMA ----------------
__global__ __launch_bounds__(128)
void k_mlp(const float* __restrict__ h,
           const float* __restrict__ lw1, const float* __restrict__ lb1,
           const float* __restrict__ lw2, const float* __restrict__ lb2,
           const float* __restrict__ lw3, const float* __restrict__ lb3,
           float* __restrict__ out) {
    __shared__ float s_w1[64 * 64];
    __shared__ float s_w2[64 * 32];
    __shared__ float s_w3[32];
    __shared__ float s_b1[64];
    __shared__ float s_b2[32];
    __shared__ float s_b3;
    int t = threadIdx.x;
    for (int i = t; i < 64 * 16; i += 128) ((float4*)s_w1)[i] = ((const float4*)lw1)[i];
    for (int i = t; i < 64 * 8;  i += 128) ((float4*)s_w2)[i] = ((const float4*)lw2)[i];
    if (t < 32) s_w3[t] = lw3[t];
    if (t < 64) s_b1[t] = lb1[t];
    if (t < 32) s_b2[t] = lb2[t];
    if (t == 0) s_b3 = lb3[0];
    __syncthreads();

    int v = blockIdx.x * 128 + t;
    if (v >= NN) return;

    float in[64];
    const float4* hr = (const float4*)(h + (size_t)v * 64);
    #pragma unroll
    for (int i = 0; i < 16; i++) {
        float4 q = hr[i];
        in[4 * i + 0] = q.x; in[4 * i + 1] = q.y;
        in[4 * i + 2] = q.z; in[4 * i + 3] = q.w;
    }

    // layer1: 64 -> 64, packed pairs
    ull a1[32];
    #pragma unroll
    for (int j = 0; j < 32; j++) a1[j] = ((const ull*)s_b1)[j];
    #pragma unroll
    for (int k = 0; k < 64; k++) {
        ull xs2 = bcast2(in[k]);
        const ull* wr = (const ull*)&s_w1[k * 64];
        #pragma unroll
        for (int j = 0; j < 32; j++) ffma2(a1[j], xs2, wr[j]);
    }
    float t1[64];
    #pragma unroll
    for (int j = 0; j < 32; j++) {
        float2 f = *(float2*)&a1[j];
        t1[2 * j]     = fmaxf(f.x, 0.f);
        t1[2 * j + 1] = fmaxf(f.y, 0.f);
    }

    // layer2: 64 -> 32, packed pairs
    ull a2[16];
    #pragma unroll
    for (int j = 0; j < 16; j++) a2[j] = ((const ull*)s_b2)[j];
    #pragma unroll
    for (int k = 0; k < 64; k++) {
        ull xs2 = bcast2(t1[k]);
        const ull* wr = (const ull*)&s_w2[k * 32];
        #pragma unroll
        for (int j = 0; j < 16; j++) ffma2(a2[j], xs2, wr[j]);
    }
    float t2[32];
    #pragma unroll
    for (int j = 0; j < 16; j++) {
        float2 f = *(float2*)&a2[j];
        t2[2 * j]     = fmaxf(f.x, 0.f);
        t2[2 * j + 1] = fmaxf(f.y, 0.f);
    }

    // layer3: 32 -> 1
    float o = s_b3;
    #pragma unroll
    for (int k = 0; k < 32; k++) o += t2[k] * s_w3[k];
    out[v] = o;
}

// ---------------- launcher ----------------
extern "C" void kernel_launch(void* const* d_in, const int* in_sizes, int n_in,
                              void* d_out, int out_size) {
    const float* x   = (const float*)d_in[0];
    const void*  edg = d_in[1];
    const float* W1  = (const float*)d_in[2];
    const float* b1  = (const float*)d_in[3];
    const float* W2  = (const float*)d_in[4];
    const float* b2  = (const float*)d_in[5];
    const float* lw1 = (const float*)d_in[6];
    const float* lb1 = (const float*)d_in[7];
    const float* lw2 = (const float*)d_in[8];
    const float* lb2 = (const float*)d_in[9];
    const float* lw3 = (const float*)d_in[10];
    const float* lb3 = (const float*)d_in[11];
    float* out = (float*)d_out;

    float* h1; cudaGetSymbolAddress((void**)&h1, g_h1);
    float* h2; cudaGetSymbolAddress((void**)&h2, g_h2);

    const int EB = (EE + 255) / 256;

    k_detect<<<1, 32>>>(edg);
    k_zero<<<(NN + 1023) / 1024, 1024>>>();
    k_hist<<<EB, 256>>>(edg);
    k_blocksum<<<NB, 1024>>>();
    k_scansums<<<1, 32>>>();
    k_blockscan<<<NB, 1024>>>();
    k_fill<<<EB, 256>>>(edg);

    // conv1: h1 = x @ W1 ; h2 = aggregate(h1) + b1
    k_gemm<128><<<(NN + 255) / 256, 256>>>(x, W1, h1);
    k_agg<<<(NN + 7) / 8, 256>>>(h1, b1, h2);

    // conv2: h1 = h2 @ W2 ; h2 = aggregate(h1) + b2
    k_gemm<64><<<(NN + 255) / 256, 256>>>(h2, W2, h1);
    k_agg<<<(NN + 7) / 8, 256>>>(h1, b2, h2);

    // MLP head
    k_mlp<<<(NN + 127) / 128, 128>>>(h2, lw1, lb1, lw2, lb2, lw3, lb3, out);
}

// round 3
// speedup vs baseline: 1.3242x; 1.0660x over previous
#include <cuda_runtime.h>
#include <cuda_fp16.h>
#include <math.h>

#define NN 100000
#define EE 3200000
#define NB 98   // (NN+1023)/1024 blocks for the scan

typedef unsigned long long ull;

// ---------------- scratch (__device__ globals; no allocs allowed) ----------------
__device__ __half2 g_hh[(size_t)NN * 32];  // 12.8 MB  (h * dinv[row], fp16)
__device__ float   g_hf[(size_t)NN * 64];  // 25.6 MB  (agg output, fp32)
__device__ int     g_counts[NN];
__device__ int     g_offsets[NN + 1];
__device__ int     g_cursor[NN];
__device__ int     g_csr[EE];              // 12.8 MB (src sorted by dst)
__device__ float   g_dinv[NN];
__device__ int     g_bsums[NB];
__device__ int     g_is64;

// ---------------- packed f32x2 helpers ----------------
__device__ __forceinline__ void ffma2(ull& d, ull a, ull b) {
    asm("fma.rn.f32x2 %0, %1, %2, %0;" : "+l"(d) : "l"(a), "l"(b));
}
__device__ __forceinline__ ull bcast2(float x) {
    unsigned u = __float_as_uint(x);
    return ((ull)u << 32) | (ull)u;
}

// ---------------- dtype detection: int64 vs int32 edge_index ----------------
__global__ void k_detect(const void* edges) {
    if (blockIdx.x == 0 && threadIdx.x == 0) {
        const unsigned* w = (const unsigned*)edges;
        int is64 = 1;
        #pragma unroll
        for (int i = 1; i < 64; i += 2) {
            if (w[i] != 0u) { is64 = 0; break; }
        }
        g_is64 = is64;
    }
}

__device__ __forceinline__ int edge_val(const void* p, long long i, int is64) {
    if (is64) return (int)((const long long*)p)[i];
    return ((const int*)p)[i];
}

// ---------------- zero counts ----------------
__global__ void k_zero() {
    int i = blockIdx.x * blockDim.x + threadIdx.x;
    if (i < NN) g_counts[i] = 0;
}

// ---------------- in-degree histogram over dst ----------------
__global__ void k_hist(const void* edges) {
    int e = blockIdx.x * blockDim.x + threadIdx.x;
    if (e >= EE) return;
    int is64 = g_is64;
    int d = edge_val(edges, (long long)EE + e, is64);
    atomicAdd(&g_counts[d], 1);
}

// ---------------- parallel scan, phase 1: per-block sums ----------------
__global__ __launch_bounds__(1024)
void k_blocksum() {
    __shared__ int wsum[32];
    int t = threadIdx.x, lane = t & 31, wid = t >> 5;
    int idx = blockIdx.x * 1024 + t;
    int v = (idx < NN) ? g_counts[idx] : 0;
    #pragma unroll
    for (int off = 16; off > 0; off >>= 1)
        v += __shfl_down_sync(0xffffffffu, v, off);
    if (lane == 0) wsum[wid] = v;
    __syncthreads();
    if (wid == 0) {
        int s = wsum[lane];
        #pragma unroll
        for (int off = 16; off > 0; off >>= 1)
            s += __shfl_down_sync(0xffffffffu, s, off);
        if (lane == 0) g_bsums[blockIdx.x] = s;
    }
}

// ---------------- phase 2: 1-warp exclusive scan of block sums ----------------
__global__ void k_scansums() {
    int lane = threadIdx.x;
    int carry = 0;
    for (int base = 0; base < NB; base += 32) {
        int i = base + lane;
        int v = (i < NB) ? g_bsums[i] : 0;
        int x = v;
        #pragma unroll
        for (int off = 1; off < 32; off <<= 1) {
            int y = __shfl_up_sync(0xffffffffu, x, off);
            if (lane >= off) x += y;
        }
        if (i < NB) g_bsums[i] = carry + x - v;
        carry += __shfl_sync(0xffffffffu, x, 31);
    }
    if (lane == 0) g_offsets[NN] = carry;
}

// ---------------- phase 3: per-block scan + apply ----------------
__global__ __launch_bounds__(1024)
void k_blockscan() {
    __shared__ int wsum[32];
    int t = threadIdx.x, lane = t & 31, wid = t >> 5;
    int idx = blockIdx.x * 1024 + t;
    int v = (idx < NN) ? g_counts[idx] : 0;
    int x = v;
    #pragma unroll
    for (int off = 1; off < 32; off <<= 1) {
        int y = __shfl_up_sync(0xffffffffu, x, off);
        if (lane >= off) x += y;
    }
    if (lane == 31) wsum[wid] = x;
    __syncthreads();
    if (wid == 0) {
        int s = wsum[lane];
        #pragma unroll
        for (int off = 1; off < 32; off <<= 1) {
            int y = __shfl_up_sync(0xffffffffu, s, off);
            if (lane >= off) s += y;
        }
        wsum[lane] = s;
    }
    __syncthreads();
    if (idx < NN) {
        int excl = g_bsums[blockIdx.x] + x - v + (wid > 0 ? wsum[wid - 1] : 0);
        g_offsets[idx] = excl;
        g_cursor[idx]  = excl;
        g_dinv[idx]    = rsqrtf((float)(v + 1));
    }
}

// ---------------- CSR fill ----------------
__global__ void k_fill(const void* edges) {
    int e = blockIdx.x * blockDim.x + threadIdx.x;
    if (e >= EE) return;
    int is64 = g_is64;
    int s = edge_val(edges, e, is64);
    int d = edge_val(edges, (long long)EE + e, is64);
    int pos = atomicAdd(&g_cursor[d], 1);
    g_csr[pos] = s;
}

// ---------------- GEMM: H'[r] = (X[r] @ W) * dinv[r], output fp16 ----------------
template <int K>
__global__ __launch_bounds__(256)
void k_gemm(const float* __restrict__ X, const float* __restrict__ W,
            __half2* __restrict__ C) {
    __shared__ float Ws[K * 64];
    for (int i = threadIdx.x; i < K * 16; i += 256) {
        ((float4*)Ws)[i] = ((const float4*)W)[i];
    }
    __syncthreads();
    int r = blockIdx.x * 256 + threadIdx.x;
    if (r >= NN) return;

    ull acc[32];
    #pragma unroll
    for (int j = 0; j < 32; j++) acc[j] = 0ull;

    const float4* xr = (const float4*)(X + (size_t)r * K);
    #pragma unroll 2
    for (int k4 = 0; k4 < K / 4; k4++) {
        float4 xv = xr[k4];
        float xk[4] = {xv.x, xv.y, xv.z, xv.w};
        #pragma unroll
        for (int kk = 0; kk < 4; kk++) {
            const ull* wr = (const ull*)&Ws[(k4 * 4 + kk) * 64];
            ull xs2 = bcast2(xk[kk]);
            #pragma unroll
            for (int j = 0; j < 32; j++) ffma2(acc[j], xs2, wr[j]);
        }
    }
    float dv = g_dinv[r];
    __half2 hv[32];
    #pragma unroll
    for (int j = 0; j < 32; j++) {
        float2 f = *(float2*)&acc[j];
        hv[j] = __floats2half2_rn(f.x * dv, f.y * dv);
    }
    uint4* cr = (uint4*)(C + (size_t)r * 32);
    const uint4* hv4 = (const uint4*)hv;
    #pragma unroll
    for (int j = 0; j < 8; j++) cr[j] = hv4[j];
}

// ---------------- aggregation: out[v] = dinv[v]*(sum_e h'[src] + h'[v]) + b
// h' already pre-scaled by dinv[src]. warp per node; lane = channels {2l,2l+1}.
__global__ __launch_bounds__(256)
void k_agg(const __half2* __restrict__ H, const float* __restrict__ b,
           float* __restrict__ out) {
    int v = blockIdx.x * 8 + (threadIdx.x >> 5);
    int lane = threadIdx.x & 31;
    if (v >= NN) return;
    int beg = g_offsets[v];
    int end = g_offsets[v + 1];
    float dv = g_dinv[v];

    float2 accA = make_float2(0.f, 0.f);
    float2 accB = make_float2(0.f, 0.f);

    for (int e = beg; e < end; e += 32) {
        int cnt = min(32, end - e);
        int s = 0;
        if (lane < cnt) s = g_csr[e + lane];
        int i = 0;
        for (; i + 1 < cnt; i += 2) {
            int si0 = __shfl_sync(0xffffffffu, s, i);
            int si1 = __shfl_sync(0xffffffffu, s, i + 1);
            float2 a = __half22float2(H[(size_t)si0 * 32 + lane]);
            float2 c = __half22float2(H[(size_t)si1 * 32 + lane]);
            accA.x += a.x; accA.y += a.y;
            accB.x += c.x; accB.y += c.y;
        }
        if (i < cnt) {
            int si = __shfl_sync(0xffffffffu, s, i);
            float2 a = __half22float2(H[(size_t)si * 32 + lane]);
            accA.x += a.x; accA.y += a.y;
        }
    }
    float2 hv = __half22float2(H[(size_t)v * 32 + lane]);
    float ax = accA.x + accB.x + hv.x;
    float ay = accA.y + accB.y + hv.y;
    float2 bb = ((const float2*)b)[lane];
    float2 o;
    o.x = ax * dv + bb.x;
    o.y = ay * dv + bb.y;
    ((float2*)out)[(size_t)v * 32 + lane] = o;
}

// ---------------- fused MLP head, packed f32x2 FMA ----------------
__global__ __launch_bounds__(128)
void k_mlp(const float* __restrict__ h,
           const float* __restrict__ lw1, const float* __restrict__ lb1,
           const float* __restrict__ lw2, const float* __restrict__ lb2,
           const float* __restrict__ lw3, const float* __restrict__ lb3,
           float* __restrict__ out) {
    __shared__ float s_w1[64 * 64];
    __shared__ float s_w2[64 * 32];
    __shared__ float s_w3[32];
    __shared__ float s_b1[64];
    __shared__ float s_b2[32];
    __shared__ float s_b3;
    int t = threadIdx.x;
    for (int i = t; i < 64 * 16; i += 128) ((float4*)s_w1)[i] = ((const float4*)lw1)[i];
    for (int i = t; i < 64 * 8;  i += 128) ((float4*)s_w2)[i] = ((const float4*)lw2)[i];
    if (t < 32) s_w3[t] = lw3[t];
    if (t < 64) s_b1[t] = lb1[t];
    if (t < 32) s_b2[t] = lb2[t];
    if (t == 0) s_b3 = lb3[0];
    __syncthreads();

    int v = blockIdx.x * 128 + t;
    if (v >= NN) return;

    float in[64];
    const float4* hr = (const float4*)(h + (size_t)v * 64);
    #pragma unroll
    for (int i = 0; i < 16; i++) {
        float4 q = hr[i];
        in[4 * i + 0] = q.x; in[4 * i + 1] = q.y;
        in[4 * i + 2] = q.z; in[4 * i + 3] = q.w;
    }

    // layer1: 64 -> 64
    ull a1[32];
    #pragma unroll
    for (int j = 0; j < 32; j++) a1[j] = ((const ull*)s_b1)[j];
    #pragma unroll
    for (int k = 0; k < 64; k++) {
        ull xs2 = bcast2(in[k]);
        const ull* wr = (const ull*)&s_w1[k * 64];
        #pragma unroll
        for (int j = 0; j < 32; j++) ffma2(a1[j], xs2, wr[j]);
    }
    float t1[64];
    #pragma unroll
    for (int j = 0; j < 32; j++) {
        float2 f = *(float2*)&a1[j];
        t1[2 * j]     = fmaxf(f.x, 0.f);
        t1[2 * j + 1] = fmaxf(f.y, 0.f);
    }

    // layer2: 64 -> 32
    ull a2[16];
    #pragma unroll
    for (int j = 0; j < 16; j++) a2[j] = ((const ull*)s_b2)[j];
    #pragma unroll
    for (int k = 0; k < 64; k++) {
        ull xs2 = bcast2(t1[k]);
        const ull* wr = (const ull*)&s_w2[k * 32];
        #pragma unroll
        for (int j = 0; j < 16; j++) ffma2(a2[j], xs2, wr[j]);
    }
    float t2[32];
    #pragma unroll
    for (int j = 0; j < 16; j++) {
        float2 f = *(float2*)&a2[j];
        t2[2 * j]     = fmaxf(f.x, 0.f);
        t2[2 * j + 1] = fmaxf(f.y, 0.f);
    }

    // layer3: 32 -> 1
    float o = s_b3;
    #pragma unroll
    for (int k = 0; k < 32; k++) o += t2[k] * s_w3[k];
    out[v] = o;
}

// ---------------- launcher ----------------
extern "C" void kernel_launch(void* const* d_in, const int* in_sizes, int n_in,
                              void* d_out, int out_size) {
    const float* x   = (const float*)d_in[0];
    const void*  edg = d_in[1];
    const float* W1  = (const float*)d_in[2];
    const float* b1  = (const float*)d_in[3];
    const float* W2  = (const float*)d_in[4];
    const float* b2  = (const float*)d_in[5];
    const float* lw1 = (const float*)d_in[6];
    const float* lb1 = (const float*)d_in[7];
    const float* lw2 = (const float*)d_in[8];
    const float* lb2 = (const float*)d_in[9];
    const float* lw3 = (const float*)d_in[10];
    const float* lb3 = (const float*)d_in[11];
    float* out = (float*)d_out;

    __half2* hh; cudaGetSymbolAddress((void**)&hh, g_hh);
    float*   hf; cudaGetSymbolAddress((void**)&hf, g_hf);

    const int EB = (EE + 255) / 256;

    k_detect<<<1, 32>>>(edg);
    k_zero<<<(NN + 1023) / 1024, 1024>>>();
    k_hist<<<EB, 256>>>(edg);
    k_blocksum<<<NB, 1024>>>();
    k_scansums<<<1, 32>>>();
    k_blockscan<<<NB, 1024>>>();
    k_fill<<<EB, 256>>>(edg);

    // conv1: hh = (x @ W1) * dinv ; hf = aggregate(hh) + b1
    k_gemm<128><<<(NN + 255) / 256, 256>>>(x, W1, hh);
    k_agg<<<(NN + 7) / 8, 256>>>(hh, b1, hf);

    // conv2: hh = (hf @ W2) * dinv ; hf = aggregate(hh) + b2
    k_gemm<64><<<(NN + 255) / 256, 256>>>(hf, W2, hh);
    k_agg<<<(NN + 7) / 8, 256>>>(hh, b2, hf);

    // MLP head
    k_mlp<<<(NN + 127) / 128, 128>>>(hf, lw1, lb1, lw2, lb2, lw3, lb3, out);
}

// round 4
// speedup vs baseline: 1.3712x; 1.0355x over previous
#include <cuda_runtime.h>
#include <cuda_fp16.h>
#include <math.h>

#define NN 100000
#define EE 3200000
#define NB 98   // (NN+1023)/1024 blocks for the scan

typedef unsigned long long ull;

// ---------------- scratch (__device__ globals; no allocs allowed) ----------------
__device__ __half2 g_hh[(size_t)NN * 32];  // 12.8 MB  (h * dinv[row], fp16)
__device__ float   g_hf[(size_t)NN * 64];  // 25.6 MB  (agg output, fp32)
__device__ int     g_counts[NN];
__device__ int     g_offsets[NN + 1];
__device__ int     g_cursor[NN];
__device__ int     g_csr[EE];              // 12.8 MB (src sorted by dst)
__device__ float   g_dinv[NN];
__device__ int     g_bsums[NB];
__device__ int     g_is64;

// ---------------- packed f32x2 helpers ----------------
__device__ __forceinline__ void ffma2(ull& d, ull a, ull b) {
    asm("fma.rn.f32x2 %0, %1, %2, %0;" : "+l"(d) : "l"(a), "l"(b));
}
__device__ __forceinline__ ull bcast2(float x) {
    unsigned u = __float_as_uint(x);
    return ((ull)u << 32) | (ull)u;
}

__device__ __forceinline__ int edge_val(const void* p, long long i, int is64) {
    if (is64) return (int)((const long long*)p)[i];
    return ((const int*)p)[i];
}

// ---------------- zero counts + dtype detect (fused) ----------------
__global__ void k_zero_detect(const void* edges) {
    int i = blockIdx.x * blockDim.x + threadIdx.x;
    if (i < NN) g_counts[i] = 0;
    if (i == 0) {
        const unsigned* w = (const unsigned*)edges;
        int is64 = 1;
        #pragma unroll
        for (int k = 1; k < 64; k += 2) {
            if (w[k] != 0u) { is64 = 0; break; }
        }
        g_is64 = is64;
    }
}

// ---------------- in-degree histogram over dst ----------------
__global__ void k_hist(const void* edges) {
    int e = blockIdx.x * blockDim.x + threadIdx.x;
    if (e >= EE) return;
    int is64 = g_is64;
    int d = edge_val(edges, (long long)EE + e, is64);
    atomicAdd(&g_counts[d], 1);
}

// ---------------- parallel scan, phase 1: per-block sums ----------------
__global__ __launch_bounds__(1024)
void k_blocksum() {
    __shared__ int wsum[32];
    int t = threadIdx.x, lane = t & 31, wid = t >> 5;
    int idx = blockIdx.x * 1024 + t;
    int v = (idx < NN) ? g_counts[idx] : 0;
    #pragma unroll
    for (int off = 16; off > 0; off >>= 1)
        v += __shfl_down_sync(0xffffffffu, v, off);
    if (lane == 0) wsum[wid] = v;
    __syncthreads();
    if (wid == 0) {
        int s = wsum[lane];
        #pragma unroll
        for (int off = 16; off > 0; off >>= 1)
            s += __shfl_down_sync(0xffffffffu, s, off);
        if (lane == 0) g_bsums[blockIdx.x] = s;
    }
}

// ---------------- phase 2: 1-warp exclusive scan of block sums ----------------
__global__ void k_scansums() {
    int lane = threadIdx.x;
    int carry = 0;
    for (int base = 0; base < NB; base += 32) {
        int i = base + lane;
        int v = (i < NB) ? g_bsums[i] : 0;
        int x = v;
        #pragma unroll
        for (int off = 1; off < 32; off <<= 1) {
            int y = __shfl_up_sync(0xffffffffu, x, off);
            if (lane >= off) x += y;
        }
        if (i < NB) g_bsums[i] = carry + x - v;
        carry += __shfl_sync(0xffffffffu, x, 31);
    }
    if (lane == 0) g_offsets[NN] = carry;
}

// ---------------- phase 3: per-block scan + apply ----------------
__global__ __launch_bounds__(1024)
void k_blockscan() {
    __shared__ int wsum[32];
    int t = threadIdx.x, lane = t & 31, wid = t >> 5;
    int idx = blockIdx.x * 1024 + t;
    int v = (idx < NN) ? g_counts[idx] : 0;
    int x = v;
    #pragma unroll
    for (int off = 1; off < 32; off <<= 1) {
        int y = __shfl_up_sync(0xffffffffu, x, off);
        if (lane >= off) x += y;
    }
    if (lane == 31) wsum[wid] = x;
    __syncthreads();
    if (wid == 0) {
        int s = wsum[lane];
        #pragma unroll
        for (int off = 1; off < 32; off <<= 1) {
            int y = __shfl_up_sync(0xffffffffu, s, off);
            if (lane >= off) s += y;
        }
        wsum[lane] = s;
    }
    __syncthreads();
    if (idx < NN) {
        int excl = g_bsums[blockIdx.x] + x - v + (wid > 0 ? wsum[wid - 1] : 0);
        g_offsets[idx] = excl;
        g_cursor[idx]  = excl;
        g_dinv[idx]    = rsqrtf((float)(v + 1));
    }
}

// ---------------- CSR fill ----------------
__global__ void k_fill(const void* edges) {
    int e = blockIdx.x * blockDim.x + threadIdx.x;
    if (e >= EE) return;
    int is64 = g_is64;
    int s = edge_val(edges, e, is64);
    int d = edge_val(edges, (long long)EE + e, is64);
    int pos = atomicAdd(&g_cursor[d], 1);
    g_csr[pos] = s;
}

// ---------------- GEMM: H'[r] = (X[r] @ W) * dinv[r], output fp16 ----------------
template <int K>
__global__ __launch_bounds__(256)
void k_gemm(const float* __restrict__ X, const float* __restrict__ W,
            __half2* __restrict__ C) {
    __shared__ float Ws[K * 64];
    for (int i = threadIdx.x; i < K * 16; i += 256) {
        ((float4*)Ws)[i] = ((const float4*)W)[i];
    }
    __syncthreads();
    int r = blockIdx.x * 256 + threadIdx.x;
    if (r >= NN) return;

    ull acc[32];
    #pragma unroll
    for (int j = 0; j < 32; j++) acc[j] = 0ull;

    const float4* xr = (const float4*)(X + (size_t)r * K);
    #pragma unroll 2
    for (int k4 = 0; k4 < K / 4; k4++) {
        float4 xv = xr[k4];
        float xk[4] = {xv.x, xv.y, xv.z, xv.w};
        #pragma unroll
        for (int kk = 0; kk < 4; kk++) {
            const ull* wr = (const ull*)&Ws[(k4 * 4 + kk) * 64];
            ull xs2 = bcast2(xk[kk]);
            #pragma unroll
            for (int j = 0; j < 32; j++) ffma2(acc[j], xs2, wr[j]);
        }
    }
    float dv = g_dinv[r];
    __half2 hv[32];
    #pragma unroll
    for (int j = 0; j < 32; j++) {
        float2 f = *(float2*)&acc[j];
        hv[j] = __floats2half2_rn(f.x * dv, f.y * dv);
    }
    uint4* cr = (uint4*)(C + (size_t)r * 32);
    const uint4* hv4 = (const uint4*)hv;
    #pragma unroll
    for (int j = 0; j < 8; j++) cr[j] = hv4[j];
}

// ---------------- aggregation: out[v] = dinv[v]*(sum_e h'[src] + h'[v]) + b
// warp per node; SMEM-staged indices; 8 outstanding row loads per batch.
__global__ __launch_bounds__(256)
void k_agg(const __half2* __restrict__ H, const float* __restrict__ b,
           float* __restrict__ out) {
    __shared__ int s_idx[8][32];
    int w = threadIdx.x >> 5;
    int v = blockIdx.x * 8 + w;
    int lane = threadIdx.x & 31;
    if (v >= NN) return;
    int beg = g_offsets[v];
    int end = g_offsets[v + 1];
    float dv = g_dinv[v];
    int* sw = s_idx[w];

    float2 a0 = make_float2(0.f, 0.f);
    float2 a1 = make_float2(0.f, 0.f);
    float2 a2 = make_float2(0.f, 0.f);
    float2 a3 = make_float2(0.f, 0.f);

    for (int e = beg; e < end; e += 32) {
        int cnt = min(32, end - e);
        if (lane < cnt) sw[lane] = g_csr[e + lane];
        __syncwarp();
        int i = 0;
        for (; i + 8 <= cnt; i += 8) {
            int s0 = sw[i + 0], s1 = sw[i + 1], s2 = sw[i + 2], s3 = sw[i + 3];
            int s4 = sw[i + 4], s5 = sw[i + 5], s6 = sw[i + 6], s7 = sw[i + 7];
            __half2 h0 = H[(size_t)s0 * 32 + lane];
            __half2 h1 = H[(size_t)s1 * 32 + lane];
            __half2 h2 = H[(size_t)s2 * 32 + lane];
            __half2 h3 = H[(size_t)s3 * 32 + lane];
            __half2 h4 = H[(size_t)s4 * 32 + lane];
            __half2 h5 = H[(size_t)s5 * 32 + lane];
            __half2 h6 = H[(size_t)s6 * 32 + lane];
            __half2 h7 = H[(size_t)s7 * 32 + lane];
            float2 f;
            f = __half22float2(h0); a0.x += f.x; a0.y += f.y;
            f = __half22float2(h1); a1.x += f.x; a1.y += f.y;
            f = __half22float2(h2); a2.x += f.x; a2.y += f.y;
            f = __half22float2(h3); a3.x += f.x; a3.y += f.y;
            f = __half22float2(h4); a0.x += f.x; a0.y += f.y;
            f = __half22float2(h5); a1.x += f.x; a1.y += f.y;
            f = __half22float2(h6); a2.x += f.x; a2.y += f.y;
            f = __half22float2(h7); a3.x += f.x; a3.y += f.y;
        }
        for (; i < cnt; i++) {
            int si = sw[i];
            float2 f = __half22float2(H[(size_t)si * 32 + lane]);
            a0.x += f.x; a0.y += f.y;
        }
        __syncwarp();
    }
    float2 hv = __half22float2(H[(size_t)v * 32 + lane]);
    float ax = a0.x + a1.x + a2.x + a3.x + hv.x;
    float ay = a0.y + a1.y + a2.y + a3.y + hv.y;
    float2 bb = ((const float2*)b)[lane];
    float2 o;
    o.x = ax * dv + bb.x;
    o.y = ay * dv + bb.y;
    ((float2*)out)[(size_t)v * 32 + lane] = o;
}

// ---------------- fused MLP head, packed f32x2 FMA ----------------
__global__ __launch_bounds__(128)
void k_mlp(const float* __restrict__ h,
           const float* __restrict__ lw1, const float* __restrict__ lb1,
           const float* __restrict__ lw2, const float* __restrict__ lb2,
           const float* __restrict__ lw3, const float* __restrict__ lb3,
           float* __restrict__ out) {
    __shared__ float s_w1[64 * 64];
    __shared__ float s_w2[64 * 32];
    __shared__ float s_w3[32];
    __shared__ float s_b1[64];
    __shared__ float s_b2[32];
    __shared__ float s_b3;
    int t = threadIdx.x;
    for (int i = t; i < 64 * 16; i += 128) ((float4*)s_w1)[i] = ((const float4*)lw1)[i];
    for (int i = t; i < 64 * 8;  i += 128) ((float4*)s_w2)[i] = ((const float4*)lw2)[i];
    if (t < 32) s_w3[t] = lw3[t];
    if (t < 64) s_b1[t] = lb1[t];
    if (t < 32) s_b2[t] = lb2[t];
    if (t == 0) s_b3 = lb3[0];
    __syncthreads();

    int v = blockIdx.x * 128 + t;
    if (v >= NN) return;

    float in[64];
    const float4* hr = (const float4*)(h + (size_t)v * 64);
    #pragma unroll
    for (int i = 0; i < 16; i++) {
        float4 q = hr[i];
        in[4 * i + 0] = q.x; in[4 * i + 1] = q.y;
        in[4 * i + 2] = q.z; in[4 * i + 3] = q.w;
    }

    // layer1: 64 -> 64
    ull a1[32];
    #pragma unroll
    for (int j = 0; j < 32; j++) a1[j] = ((const ull*)s_b1)[j];
    #pragma unroll
    for (int k = 0; k < 64; k++) {
        ull xs2 = bcast2(in[k]);
        const ull* wr = (const ull*)&s_w1[k * 64];
        #pragma unroll
        for (int j = 0; j < 32; j++) ffma2(a1[j], xs2, wr[j]);
    }
    float t1[64];
    #pragma unroll
    for (int j = 0; j < 32; j++) {
        float2 f = *(float2*)&a1[j];
        t1[2 * j]     = fmaxf(f.x, 0.f);
        t1[2 * j + 1] = fmaxf(f.y, 0.f);
    }

    // layer2: 64 -> 32
    ull a2[16];
    #pragma unroll
    for (int j = 0; j < 16; j++) a2[j] = ((const ull*)s_b2)[j];
    #pragma unroll
    for (int k = 0; k < 64; k++) {
        ull xs2 = bcast2(t1[k]);
        const ull* wr = (const ull*)&s_w2[k * 32];
        #pragma unroll
        for (int j = 0; j < 16; j++) ffma2(a2[j], xs2, wr[j]);
    }
    float t2[32];
    #pragma unroll
    for (int j = 0; j < 16; j++) {
        float2 f = *(float2*)&a2[j];
        t2[2 * j]     = fmaxf(f.x, 0.f);
        t2[2 * j + 1] = fmaxf(f.y, 0.f);
    }

    // layer3: 32 -> 1
    float o = s_b3;
    #pragma unroll
    for (int k = 0; k < 32; k++) o += t2[k] * s_w3[k];
    out[v] = o;
}

// ---------------- launcher ----------------
extern "C" void kernel_launch(void* const* d_in, const int* in_sizes, int n_in,
                              void* d_out, int out_size) {
    const float* x   = (const float*)d_in[0];
    const void*  edg = d_in[1];
    const float* W1  = (const float*)d_in[2];
    const float* b1  = (const float*)d_in[3];
    const float* W2  = (const float*)d_in[4];
    const float* b2  = (const float*)d_in[5];
    const float* lw1 = (const float*)d_in[6];
    const float* lb1 = (const float*)d_in[7];
    const float* lw2 = (const float*)d_in[8];
    const float* lb2 = (const float*)d_in[9];
    const float* lw3 = (const float*)d_in[10];
    const float* lb3 = (const float*)d_in[11];
    float* out = (float*)d_out;

    __half2* hh; cudaGetSymbolAddress((void**)&hh, g_hh);
    float*   hf; cudaGetSymbolAddress((void**)&hf, g_hf);

    const int EB = (EE + 255) / 256;

    k_zero_detect<<<(NN + 1023) / 1024, 1024>>>(edg);
    k_hist<<<EB, 256>>>(edg);
    k_blocksum<<<NB, 1024>>>();
    k_scansums<<<1, 32>>>();
    k_blockscan<<<NB, 1024>>>();
    k_fill<<<EB, 256>>>(edg);

    // conv1: hh = (x @ W1) * dinv ; hf = aggregate(hh) + b1
    k_gemm<128><<<(NN + 255) / 256, 256>>>(x, W1, hh);
    k_agg<<<(NN + 7) / 8, 256>>>(hh, b1, hf);

    // conv2: hh = (hf @ W2) * dinv ; hf = aggregate(hh) + b2
    k_gemm<64><<<(NN + 255) / 256, 256>>>(hf, W2, hh);
    k_agg<<<(NN + 7) / 8, 256>>>(hh, b2, hf);

    // MLP head
    k_mlp<<<(NN + 127) / 128, 128>>>(hf, lw1, lb1, lw2, lb2, lw3, lb3, out);
}